// round 2
// baseline (speedup 1.0000x reference)
#include <cuda_runtime.h>
#include <cstdint>
#include <cstddef>

// Problem constants (fixed by setup_inputs)
#define DIMSZ   1024
#define HD      64
#define NHEADS  16
#define BL      4096            // B*L = 2*2048
#define MROWS   2048
#define MCHUNK  128
#define NCHUNK  (MROWS / MCHUNK)   // 16
// BETA * log2(e): fold into Q so softmax runs in base 2 (single EX2 per element)
#define SCALE_LOG2 23.083120654223414f

typedef unsigned long long ull;

// ping-pong scratch (no allocations allowed)
__device__ float g_bufA[(size_t)BL * DIMSZ];
__device__ float g_bufB[(size_t)BL * DIMSZ];

// ---------------- packed f32x2 helpers ----------------
__device__ __forceinline__ ull pack2(float lo, float hi) {
    ull r; asm("mov.b64 %0, {%1, %2};" : "=l"(r) : "f"(lo), "f"(hi)); return r;
}
__device__ __forceinline__ void unpack2(ull v, float& lo, float& hi) {
    asm("mov.b64 {%0, %1}, %2;" : "=f"(lo), "=f"(hi) : "l"(v));
}
__device__ __forceinline__ void ffma2(ull& d, ull a, ull b) {
    asm("fma.rn.f32x2 %0, %1, %2, %0;" : "+l"(d) : "l"(a), "l"(b));
}
__device__ __forceinline__ ull mul2(ull a, ull b) {
    ull r; asm("mul.rn.f32x2 %0, %1, %2;" : "=l"(r) : "l"(a), "l"(b)); return r;
}
__device__ __forceinline__ float ex2(float x) {
    float r; asm("ex2.approx.f32 %0, %1;" : "=f"(r) : "f"(x)); return r;
}

// =======================================================================
// Dense linear: C[4096][1024] = A @ W^T + bias   (torch Linear, W=[out,in])
// Both A and W are k-contiguous. Tile 128x128, kt=16, 256 thr, 8x8 micro.
// =======================================================================
__global__ void __launch_bounds__(256, 2)
linear_kernel(float* __restrict__ C, const float* __restrict__ A,
              const float* __restrict__ W, const float* __restrict__ bias)
{
    __shared__ float As[16][132];   // As[k][i]
    __shared__ float Bs[16][132];   // Bs[k][j]
    const int tid = threadIdx.x;
    const int tx  = tid & 15;       // j-tile
    const int ty  = tid >> 4;       // i-tile
    const int i0  = blockIdx.y * 128;
    const int j0  = blockIdx.x * 128;

    // accumulators pre-initialized with bias (pairs along j)
    ull acc[8][4];
    {
        const float* bp = bias + j0 + tx * 8;
        float4 b0 = *(const float4*)bp;
        float4 b1 = *(const float4*)(bp + 4);
        ull p0 = pack2(b0.x, b0.y), p1 = pack2(b0.z, b0.w);
        ull p2 = pack2(b1.x, b1.y), p3 = pack2(b1.z, b1.w);
        #pragma unroll
        for (int ii = 0; ii < 8; ii++) {
            acc[ii][0] = p0; acc[ii][1] = p1; acc[ii][2] = p2; acc[ii][3] = p3;
        }
    }

    const int lk = tid & 15;        // k within tile
    const int ib = tid >> 4;        // base row

    for (int kt = 0; kt < 64; kt++) {
        __syncthreads();
        const float* Ag = A + (size_t)(i0 + ib) * DIMSZ + kt * 16 + lk;
        const float* Wg = W + (size_t)(j0 + ib) * DIMSZ + kt * 16 + lk;
        #pragma unroll
        for (int rep = 0; rep < 8; rep++) {
            As[lk][ib + rep * 16] = Ag[(size_t)rep * 16 * DIMSZ];
            Bs[lk][ib + rep * 16] = Wg[(size_t)rep * 16 * DIMSZ];
        }
        __syncthreads();
        #pragma unroll
        for (int k = 0; k < 16; k++) {
            const float* ap = &As[k][ty * 8];
            float4 a0 = *(const float4*)ap;
            float4 a1 = *(const float4*)(ap + 4);
            const float* bp = &Bs[k][tx * 8];
            ulonglong2 w0 = *(const ulonglong2*)bp;
            ulonglong2 w1 = *(const ulonglong2*)(bp + 4);
            float a[8] = {a0.x, a0.y, a0.z, a0.w, a1.x, a1.y, a1.z, a1.w};
            #pragma unroll
            for (int ii = 0; ii < 8; ii++) {
                ull ad = pack2(a[ii], a[ii]);
                ffma2(acc[ii][0], ad, w0.x);
                ffma2(acc[ii][1], ad, w0.y);
                ffma2(acc[ii][2], ad, w1.x);
                ffma2(acc[ii][3], ad, w1.y);
            }
        }
    }

    // epilogue
    #pragma unroll
    for (int ii = 0; ii < 8; ii++) {
        float4 o0, o1;
        unpack2(acc[ii][0], o0.x, o0.y);
        unpack2(acc[ii][1], o0.z, o0.w);
        unpack2(acc[ii][2], o1.x, o1.y);
        unpack2(acc[ii][3], o1.z, o1.w);
        float* cp = C + (size_t)(i0 + ty * 8 + ii) * DIMSZ + j0 + tx * 8;
        *(float4*)cp       = o0;
        *(float4*)(cp + 4) = o1;
    }
}

// =======================================================================
// Fused Hopfield retrieval (one iteration):
//   dst[r, h*64+d] = sum_m softmax_m(16 * q . mem[m]) * mem[m, d]
// CTA: 128 query rows x 1 head. Flash-style online softmax over 16 chunks.
// =======================================================================
// dynamic smem layout (floats):
#define SM_QTS   0                        // Qts[64][132]  (transposed, scaled)
#define SM_KTS   (64 * 132)               // Kts[64][132]  (transposed K chunk)
#define SM_VS    (SM_KTS + 64 * 132)      // Vs[128][68]   (straight V chunk)
#define SM_PS    (SM_VS + 128 * 68)       // Ps[128][132]  (probabilities)
#define SM_ALPHA (SM_PS + 128 * 132)      // [128]
#define SM_LSUM  (SM_ALPHA + 128)         // [128]
#define SM_FLOATS (SM_LSUM + 128)
#define SM_BYTES (SM_FLOATS * 4)          // 171008 B

__global__ void __launch_bounds__(256, 1)
hopfield_attn_kernel(float* __restrict__ dst, const float* __restrict__ src,
                     const float* __restrict__ mem)
{
    extern __shared__ float sm[];
    float* Qts    = sm + SM_QTS;
    float* Kts    = sm + SM_KTS;
    float* Vs     = sm + SM_VS;
    float* Ps     = sm + SM_PS;
    float* rAlpha = sm + SM_ALPHA;
    float* rLsum  = sm + SM_LSUM;

    const int tid = threadIdx.x;
    const int h   = blockIdx.y;
    const int r0  = blockIdx.x * 128;

    // ---- load Q, scaled by BETA*log2(e), stored transposed Qts[d][i] ----
    {
        const int i = tid & 127, seg = tid >> 7;
        const float* gq = src + (size_t)(r0 + i) * DIMSZ + h * HD + seg * 32;
        #pragma unroll
        for (int j = 0; j < 8; j++) {
            float4 v = *(const float4*)(gq + 4 * j);
            int d = seg * 32 + 4 * j;
            Qts[(d + 0) * 132 + i] = v.x * SCALE_LOG2;
            Qts[(d + 1) * 132 + i] = v.y * SCALE_LOG2;
            Qts[(d + 2) * 132 + i] = v.z * SCALE_LOG2;
            Qts[(d + 3) * 132 + i] = v.w * SCALE_LOG2;
        }
    }

    // S-phase coords: 16 q-tiles x 16 m-tiles (8x8 micro)
    const int mt = tid & 15;
    const int qt = tid >> 4;
    // PV-phase coords: 32 q-groups x 8 d-groups (4q x 8d micro), q strided by 32
    const int dg = tid & 7;
    const int qg = tid >> 3;

    float mrow[8], lrow[8];
    #pragma unroll
    for (int qi = 0; qi < 8; qi++) { mrow[qi] = -1e30f; lrow[qi] = 0.0f; }
    ull Opk[4][4];
    #pragma unroll
    for (int qi = 0; qi < 4; qi++)
        #pragma unroll
        for (int dp = 0; dp < 4; dp++) Opk[qi][dp] = 0ull;

    for (int c = 0; c < NCHUNK; c++) {
        __syncthreads();   // prev PV done reading Ps/Kts/Vs (and Q store done)
        // ---- load K chunk: Kts[d][m] transposed + Vs[m][d] straight ----
        {
            const int m = tid & 127, seg = tid >> 7;
            const float* gk = mem + (size_t)(c * 128 + m) * HD + seg * 32;
            #pragma unroll
            for (int j = 0; j < 8; j++) {
                float4 v = *(const float4*)(gk + 4 * j);
                int d = seg * 32 + 4 * j;
                Kts[(d + 0) * 132 + m] = v.x;
                Kts[(d + 1) * 132 + m] = v.y;
                Kts[(d + 2) * 132 + m] = v.z;
                Kts[(d + 3) * 132 + m] = v.w;
                *(float4*)(Vs + m * 68 + d) = v;
            }
        }
        __syncthreads();

        // ---- S = Qs @ Kc^T  (8q x 8m per thread, pairs along m) ----
        ull spk[8][4];
        #pragma unroll
        for (int qi = 0; qi < 8; qi++)
            #pragma unroll
            for (int mp = 0; mp < 4; mp++) spk[qi][mp] = 0ull;

        const float* qsp = Qts + qt * 8;
        const float* ksp = Kts + mt * 8;
        #pragma unroll 16
        for (int d = 0; d < HD; d++) {
            const float* qp = qsp + d * 132;
            float4 a0 = *(const float4*)qp;
            float4 a1 = *(const float4*)(qp + 4);
            const float* kp = ksp + d * 132;
            ulonglong2 b0 = *(const ulonglong2*)kp;
            ulonglong2 b1 = *(const ulonglong2*)(kp + 4);
            float a[8] = {a0.x, a0.y, a0.z, a0.w, a1.x, a1.y, a1.z, a1.w};
            #pragma unroll
            for (int qi = 0; qi < 8; qi++) {
                ull ad = pack2(a[qi], a[qi]);
                ffma2(spk[qi][0], ad, b0.x);
                ffma2(spk[qi][1], ad, b0.y);
                ffma2(spk[qi][2], ad, b1.x);
                ffma2(spk[qi][3], ad, b1.y);
            }
        }

        // ---- online softmax (base 2), write P + alpha ----
        #pragma unroll
        for (int qi = 0; qi < 8; qi++) {
            float s[8];
            unpack2(spk[qi][0], s[0], s[1]);
            unpack2(spk[qi][1], s[2], s[3]);
            unpack2(spk[qi][2], s[4], s[5]);
            unpack2(spk[qi][3], s[6], s[7]);
            float mx = s[0];
            #pragma unroll
            for (int j = 1; j < 8; j++) mx = fmaxf(mx, s[j]);
            #pragma unroll
            for (int o = 8; o >= 1; o >>= 1)
                mx = fmaxf(mx, __shfl_xor_sync(0xffffffffu, mx, o));
            float mnew  = fmaxf(mrow[qi], mx);
            float alpha = ex2(mrow[qi] - mnew);
            mrow[qi] = mnew;
            float rs = 0.0f;
            #pragma unroll
            for (int j = 0; j < 8; j++) { s[j] = ex2(s[j] - mnew); rs += s[j]; }
            #pragma unroll
            for (int o = 8; o >= 1; o >>= 1)
                rs += __shfl_xor_sync(0xffffffffu, rs, o);
            lrow[qi] = lrow[qi] * alpha + rs;
            const int q = qt * 8 + qi;
            if (mt == 0) rAlpha[q] = alpha;
            float4 p0 = {s[0], s[1], s[2], s[3]};
            float4 p1 = {s[4], s[5], s[6], s[7]};
            *(float4*)(Ps + q * 132 + mt * 8)     = p0;
            *(float4*)(Ps + q * 132 + mt * 8 + 4) = p1;
        }
        if (c == NCHUNK - 1 && mt == 0) {
            #pragma unroll
            for (int qi = 0; qi < 8; qi++) rLsum[qt * 8 + qi] = lrow[qi];
        }
        __syncthreads();

        // ---- O = O*alpha + P @ V  (4q x 8d per thread, q strided by 32) ----
        float al[4];
        #pragma unroll
        for (int qi = 0; qi < 4; qi++) al[qi] = rAlpha[qg + 32 * qi];
        #pragma unroll
        for (int qi = 0; qi < 4; qi++) {
            ull ap = pack2(al[qi], al[qi]);
            #pragma unroll
            for (int dp = 0; dp < 4; dp++) Opk[qi][dp] = mul2(Opk[qi][dp], ap);
        }
        #pragma unroll 8
        for (int m = 0; m < MCHUNK; m++) {
            const float* vp = Vs + m * 68 + dg * 8;
            ulonglong2 v0 = *(const ulonglong2*)vp;
            ulonglong2 v1 = *(const ulonglong2*)(vp + 4);
            #pragma unroll
            for (int qi = 0; qi < 4; qi++) {
                float p = Ps[(qg + 32 * qi) * 132 + m];
                ull pd = pack2(p, p);
                ffma2(Opk[qi][0], pd, v0.x);
                ffma2(Opk[qi][1], pd, v0.y);
                ffma2(Opk[qi][2], pd, v1.x);
                ffma2(Opk[qi][3], pd, v1.y);
            }
        }
    }

    // ---- epilogue: normalize and store ----
    #pragma unroll
    for (int qi = 0; qi < 4; qi++) {
        const int q = qg + 32 * qi;
        float inv = 1.0f / rLsum[q];
        float4 o0, o1;
        unpack2(Opk[qi][0], o0.x, o0.y);
        unpack2(Opk[qi][1], o0.z, o0.w);
        unpack2(Opk[qi][2], o1.x, o1.y);
        unpack2(Opk[qi][3], o1.z, o1.w);
        o0.x *= inv; o0.y *= inv; o0.z *= inv; o0.w *= inv;
        o1.x *= inv; o1.y *= inv; o1.z *= inv; o1.w *= inv;
        float* op = dst + (size_t)(r0 + q) * DIMSZ + h * HD + dg * 8;
        *(float4*)op       = o0;
        *(float4*)(op + 4) = o1;
    }
}

// =======================================================================
extern "C" void kernel_launch(void* const* d_in, const int* in_sizes, int n_in,
                              void* d_out, int out_size)
{
    (void)in_sizes; (void)n_in; (void)out_size;
    const float* x    = (const float*)d_in[0];
    const float* mem  = (const float*)d_in[1];
    const float* Wq   = (const float*)d_in[2];
    const float* bq   = (const float*)d_in[3];
    const float* Wo   = (const float*)d_in[4];
    const float* bo   = (const float*)d_in[5];
    float* out = (float*)d_out;

    float *bufA = nullptr, *bufB = nullptr;
    cudaGetSymbolAddress((void**)&bufA, g_bufA);
    cudaGetSymbolAddress((void**)&bufB, g_bufB);

    static bool attr_set = false;
    if (!attr_set) {
        cudaFuncSetAttribute(hopfield_attn_kernel,
                             cudaFuncAttributeMaxDynamicSharedMemorySize, SM_BYTES);
        attr_set = true;
    }

    dim3 gemm_grid(DIMSZ / 128, BL / 128);     // (8, 32)
    dim3 attn_grid(BL / 128, NHEADS);          // (32, 16)

    // q = x @ Wq^T + bq
    linear_kernel<<<gemm_grid, 256>>>(bufA, x, Wq, bq);
    // 2 Hopfield iterations (setup_inputs fixes iterations=2)
    hopfield_attn_kernel<<<attn_grid, 256, SM_BYTES>>>(bufB, bufA, mem);
    hopfield_attn_kernel<<<attn_grid, 256, SM_BYTES>>>(bufA, bufB, mem);
    // out = q @ Wo^T + bo
    linear_kernel<<<gemm_grid, 256>>>(out, bufA, Wo, bo);
}